// round 4
// baseline (speedup 1.0000x reference)
#include <cuda_runtime.h>
#include <math.h>

// Problem constants
#define BB    1024
#define KK    160
#define WSS   12
#define NG    36          // 3*WS gate width
#define DHID  1024

// ---------------- scratch (device globals; no allocation) ----------------
__device__ float g_Wt[144 * KK];                 // enc_W transposed: [(i_in*12+o)][k]
__device__ float g_bt[12 * KK];                  // enc_b transposed: [o][k]
__device__ float g_delta[KK * NG];               // per-k positional gi delta (pass 2)
__device__ float g_M[KK * 144];                  // collapsed decoder W1@W2, [k][d][o]
__device__ float g_c[KK * 12];                   // collapsed decoder bias
__device__ float g_gi[(size_t)BB * KK * NG + 64];// precomputed input gates [b][k][j]
__device__ float g_ys[(size_t)BB * KK * WSS];    // pass-2 GRU outputs [b][k][d]

// ---------------- fast activations (EX2/RCP based, ~few ulp) ----------------
__device__ __forceinline__ float sigmoidf_fast(float x) {
    float e = __expf(-x);
    return __fdividef(1.f, 1.f + e);
}
__device__ __forceinline__ float tanhf_fast(float x) {
    float e = __expf(2.f * x);                  // inf for big x -> result 1; 0 -> -1
    return 1.f - __fdividef(2.f, e + 1.f);
}

// ============================================================================
// P1: transpose encoder weights, compute positional gi-delta
//   pe12[k,2m]=sin(k*div_m), pe12[k,2m+1]=cos(k*div_m), div_m=exp(-2m*ln(1e4)/12)
//   channel_enc[k,i] = sin(k)   (ch_pe column 0)
//   delta[k][j] = sum_i (pe12[k,i]+sin(k)) * Wih[j,i]
// ============================================================================
__global__ void prep_small(const float* __restrict__ encW,
                           const float* __restrict__ encb,
                           const float* __restrict__ Wih) {
    int k = blockIdx.x;
    int t = threadIdx.x;
    if (t < 144) g_Wt[t * KK + k] = encW[k * 144 + t];
    if (t < 12)  g_bt[t * KK + k] = encb[k * 12 + t];
    if (t < 36) {
        const float LN1E4 = 9.210340371976184f;
        float sk = sinf((float)k);
        float acc = 0.f;
        #pragma unroll
        for (int i = 0; i < 12; i++) {
            int m = i >> 1;
            float div = expf(-(float)(2 * m) * (LN1E4 / 12.f));
            float ang = (float)k * div;
            float pe = (i & 1) ? cosf(ang) : sinf(ang);
            acc = fmaf(pe + sk, Wih[t * 12 + i], acc);
        }
        g_delta[k * NG + t] = acc;
    }
}

// ============================================================================
// P2: collapse decoder — M[k] = W1[k] @ W2[k] (12x12), c[k] = b1[k]@W2[k]+b2[k]
// ============================================================================
__global__ void prep_Mc(const float* __restrict__ W1, const float* __restrict__ b1,
                        const float* __restrict__ W2, const float* __restrict__ b2) {
    __shared__ float sW2[DHID * 12];             // 48KB
    int k = blockIdx.x;
    for (int idx = threadIdx.x; idx < DHID * 12; idx += blockDim.x)
        sW2[idx] = W2[(size_t)k * DHID * 12 + idx];
    __syncthreads();
    int t = threadIdx.x;
    if (t < 144) {
        int d = t / 12, o = t % 12;
        const float* w1 = W1 + (size_t)k * 12 * DHID + d * DHID;
        float acc = 0.f;
        #pragma unroll 8
        for (int h = 0; h < DHID; h++)
            acc = fmaf(w1[h], sW2[h * 12 + o], acc);
        g_M[k * 144 + t] = acc;
    } else if (t < 156) {
        int o = t - 144;
        const float* bb = b1 + (size_t)k * DHID;
        float acc = b2[k * 12 + o];
        #pragma unroll 8
        for (int h = 0; h < DHID; h++)
            acc = fmaf(bb[h], sW2[h * 12 + o], acc);
        g_c[k * 12 + o] = acc;
    }
}

// ============================================================================
// K1: encoder + input-gate precompute.
//   xs[o] = relu(sum_i x[b,k*12+i] * encW[k,i,o] + encb[k,o])
//   gi[j] = sum_o xs[o]*Wih[j,o] + bih[j] + (j<24 ? bhh[j] : 0)
//   (bhh_n stays in the scan because reference does n = tanh(inn + r*(h·Whh_n+bhh_n)))
// Thread t = b*160+k -> coalesced x reads (float4) and coalesced gi writes.
// enc weights accessed through the k-transposed copies -> coalesced.
// ============================================================================
__global__ void enc_gi(const float* __restrict__ x,
                       const float* __restrict__ Wih,
                       const float* __restrict__ bih,
                       const float* __restrict__ bhh) {
    __shared__ float sW[NG * 12];
    __shared__ float sB[NG];
    for (int i = threadIdx.x; i < NG * 12; i += blockDim.x) sW[i] = Wih[i];
    for (int i = threadIdx.x; i < NG; i += blockDim.x)
        sB[i] = bih[i] + (i < 24 ? bhh[i] : 0.f);
    __syncthreads();

    int t = blockIdx.x * blockDim.x + threadIdx.x;     // [0, B*K)
    int b = t / KK, k = t - b * KK;

    const float4* xv = reinterpret_cast<const float4*>(x) + (size_t)b * 480 + k * 3;
    float4 v0 = xv[0], v1 = xv[1], v2 = xv[2];
    float xm[12] = {v0.x, v0.y, v0.z, v0.w, v1.x, v1.y, v1.z, v1.w,
                    v2.x, v2.y, v2.z, v2.w};

    float xs[12];
    #pragma unroll
    for (int o = 0; o < 12; o++) {
        float acc = g_bt[o * KK + k];
        #pragma unroll
        for (int i = 0; i < 12; i++)
            acc = fmaf(xm[i], g_Wt[(i * 12 + o) * KK + k], acc);
        xs[o] = fmaxf(acc, 0.f);
    }

    float* out = g_gi + (size_t)t * NG;
    #pragma unroll
    for (int j = 0; j < NG; j++) {
        float acc = sB[j];
        #pragma unroll
        for (int i = 0; i < 12; i++)
            acc = fmaf(xs[i], sW[j * 12 + i], acc);
        out[j] = acc;
    }
}

// ============================================================================
// K2: the sequential GRU scan. 12 lanes per chain, 2 chains per warp (16-lane
// groups), h broadcast via shuffles. gi prefetched 2 steps ahead (L2 hit ~250cy).
// Pass 1 (k=0..159, h0=0) -> pass 2 (gi + delta, stores ys).
// ============================================================================
__device__ __forceinline__ float gru_step(float h, float gr, float gz, float gn,
                                          const float* wr, const float* wz,
                                          const float* wn, float bn, int gbase) {
    float ar0 = 0.f, az0 = 0.f, an0 = bn;       // bhh_n folded into n-accumulator
    float ar1 = 0.f, az1 = 0.f, an1 = 0.f;
    #pragma unroll
    for (int i = 0; i < 6; i++) {
        float hv = __shfl_sync(0xffffffffu, h, gbase + i);
        ar0 = fmaf(wr[i], hv, ar0);
        az0 = fmaf(wz[i], hv, az0);
        an0 = fmaf(wn[i], hv, an0);
    }
    #pragma unroll
    for (int i = 6; i < 12; i++) {
        float hv = __shfl_sync(0xffffffffu, h, gbase + i);
        ar1 = fmaf(wr[i], hv, ar1);
        az1 = fmaf(wz[i], hv, az1);
        an1 = fmaf(wn[i], hv, an1);
    }
    float r = sigmoidf_fast(gr + (ar0 + ar1));
    float z = sigmoidf_fast(gz + (az0 + az1));
    float n = tanhf_fast(fmaf(r, an0 + an1, gn));
    return fmaf(z, h - n, n);                    // (1-z)*n + z*h
}

__global__ void __launch_bounds__(64) scan_gru(const float* __restrict__ Whh,
                                               const float* __restrict__ bhh) {
    const int lane  = threadIdx.x & 31;
    const int sub   = threadIdx.x & 15;
    const int s     = sub < 12 ? sub : 11;       // lanes 12-15: duplicate lane 11
    const int gbase = lane & 16;
    const int chain = blockIdx.x * 4 + (threadIdx.x >> 4);

    float wr[12], wz[12], wn[12];
    #pragma unroll
    for (int i = 0; i < 12; i++) {
        wr[i] = Whh[s * 12 + i];
        wz[i] = Whh[(s + 12) * 12 + i];
        wn[i] = Whh[(s + 24) * 12 + i];
    }
    float bn = bhh[24 + s];

    const float* gp = g_gi + (size_t)chain * (KK * NG);
    float h = 0.f;

    // -------- pass 1 --------
    float A0 = gp[s], B0 = gp[12 + s], C0 = gp[24 + s];
    float A1 = gp[NG + s], B1 = gp[NG + 12 + s], C1 = gp[NG + 24 + s];
    #pragma unroll 2
    for (int k = 0; k < KK; k++) {
        float gr, gz, gn;
        if ((k & 1) == 0) {
            gr = A0; gz = B0; gn = C0;
            if (k + 2 < KK) { const float* p = gp + (k + 2) * NG;
                A0 = p[s]; B0 = p[12 + s]; C0 = p[24 + s]; }
        } else {
            gr = A1; gz = B1; gn = C1;
            if (k + 2 < KK) { const float* p = gp + (k + 2) * NG;
                A1 = p[s]; B1 = p[12 + s]; C1 = p[24 + s]; }
        }
        h = gru_step(h, gr, gz, gn, wr, wz, wn, bn, gbase);
    }

    // -------- pass 2 (gi + per-k delta), store outputs --------
    float* yp = g_ys + (size_t)chain * (KK * WSS);
    float D0, E0, F0, D1, E1, F1;
    A0 = gp[s];      B0 = gp[12 + s];      C0 = gp[24 + s];
    D0 = g_delta[s]; E0 = g_delta[12 + s]; F0 = g_delta[24 + s];
    A1 = gp[NG + s];      B1 = gp[NG + 12 + s];      C1 = gp[NG + 24 + s];
    D1 = g_delta[NG + s]; E1 = g_delta[NG + 12 + s]; F1 = g_delta[NG + 24 + s];
    #pragma unroll 2
    for (int k = 0; k < KK; k++) {
        float gr, gz, gn;
        if ((k & 1) == 0) {
            gr = A0 + D0; gz = B0 + E0; gn = C0 + F0;
            if (k + 2 < KK) {
                const float* p = gp + (k + 2) * NG;
                const float* q = g_delta + (k + 2) * NG;
                A0 = p[s]; B0 = p[12 + s]; C0 = p[24 + s];
                D0 = q[s]; E0 = q[12 + s]; F0 = q[24 + s];
            }
        } else {
            gr = A1 + D1; gz = B1 + E1; gn = C1 + F1;
            if (k + 2 < KK) {
                const float* p = gp + (k + 2) * NG;
                const float* q = g_delta + (k + 2) * NG;
                A1 = p[s]; B1 = p[12 + s]; C1 = p[24 + s];
                D1 = q[s]; E1 = q[12 + s]; F1 = q[24 + s];
            }
        }
        h = gru_step(h, gr, gz, gn, wr, wz, wn, bn, gbase);
        if (sub < 12) yp[k * 12 + sub] = h;
    }
}

// ============================================================================
// K3: apply collapsed decoder: res[b,k,o] = sum_d ys[b,k,d]*M[k,d,o] + c[k,o]
// ============================================================================
__global__ void decode(float* __restrict__ out) {
    int tid = blockIdx.x * blockDim.x + threadIdx.x;  // [0, B*1920)
    int o  = tid % 12;
    int bk = tid / 12;                                // b*160 + k
    int k  = bk % KK;
    const float* y = g_ys + (size_t)bk * 12;
    const float* m = g_M + k * 144 + o;
    float acc = g_c[k * 12 + o];
    #pragma unroll
    for (int d = 0; d < 12; d++)
        acc = fmaf(y[d], m[d * 12], acc);
    out[tid] = acc;
}

// ============================================================================
extern "C" void kernel_launch(void* const* d_in, const int* in_sizes, int n_in,
                              void* d_out, int out_size) {
    const float* x    = (const float*)d_in[0];
    const float* encW = (const float*)d_in[1];
    const float* encb = (const float*)d_in[2];
    const float* Wih  = (const float*)d_in[3];
    const float* Whh  = (const float*)d_in[4];
    const float* bih  = (const float*)d_in[5];
    const float* bhh  = (const float*)d_in[6];
    const float* W1   = (const float*)d_in[7];
    const float* b1   = (const float*)d_in[8];
    const float* W2   = (const float*)d_in[9];
    const float* b2   = (const float*)d_in[10];
    float* out = (float*)d_out;

    prep_small<<<KK, 160>>>(encW, encb, Wih);
    prep_Mc<<<KK, 256>>>(W1, b1, W2, b2);
    enc_gi<<<(BB * KK) / 256, 256>>>(x, Wih, bih, bhh);
    scan_gru<<<BB / 4, 64>>>(Whh, bhh);
    decode<<<(BB * KK * 12) / 256, 256>>>(out);
}

// round 5
// speedup vs baseline: 1.3951x; 1.3951x over previous
#include <cuda_runtime.h>
#include <math.h>

// Problem constants
#define BB    1024
#define KK    160
#define NG    36          // 3*WS gate width
#define DHID  1024

// ---------------- scratch (device globals; no allocation) ----------------
__device__ float g_Wt[144 * KK];                  // enc_W transposed: [(i*12+o)][k]
__device__ float g_bt[12 * KK];                   // enc_b transposed: [o][k]
__device__ float g_delta[NG * KK];                // positional gi delta, [j][k], j<24 pre-halved
__device__ float g_Mc[KK * 192];                  // per-k decoder: [k][o][0..11]=W1@W2 col, [12]=bias
__device__ float g_gi[(size_t)BB * NG * KK + 16]; // input gates, [b][j][k], j<24 pre-halved

// ---------------- activations ----------------
__device__ __forceinline__ float tanh_ap(float x) {      // HW tanh (sm_75+)
    float y; asm("tanh.approx.f32 %0, %1;" : "=f"(y) : "f"(x)); return y;
}
__device__ __forceinline__ float tanh_acc(float x) {     // accurate, EX2/RCP based
    float e = __expf(2.f * x);
    return 1.f - __fdividef(2.f, e + 1.f);
}

// ============================================================================
// P: all prep — encoder weight transpose, positional delta, collapsed decoder.
//   M[k] = dec_W1[k] @ dec_W2[k] (12x12), c[k] = b1[k]@W2[k]+b2[k]
//   (decoder has no nonlinearity between W1 and W2, so it collapses exactly)
// ============================================================================
__global__ void prep_all(const float* __restrict__ encW, const float* __restrict__ encb,
                         const float* __restrict__ Wih,
                         const float* __restrict__ W1, const float* __restrict__ b1,
                         const float* __restrict__ W2, const float* __restrict__ b2) {
    __shared__ float sW2[DHID * 12];              // 48KB
    int k = blockIdx.x, t = threadIdx.x;
    for (int i = t; i < DHID * 12; i += blockDim.x)
        sW2[i] = W2[(size_t)k * DHID * 12 + i];

    if (t < 144) g_Wt[t * KK + k] = encW[k * 144 + t];
    if (t < 12)  g_bt[t * KK + k] = encb[k * 12 + t];
    if (t < 36) {
        // delta[k][j] = sum_i (pe12[k,i] + sin(k)) * Wih[j,i]  (pass-2 input shift)
        const float LN1E4 = 9.210340371976184f;
        float sk = sinf((float)k);
        float acc = 0.f;
        #pragma unroll
        for (int i = 0; i < 12; i++) {
            int m = i >> 1;
            float div = expf(-(float)(2 * m) * (LN1E4 / 12.f));
            float ang = (float)k * div;
            float pe = (i & 1) ? cosf(ang) : sinf(ang);
            acc = fmaf(pe + sk, Wih[t * 12 + i], acc);
        }
        g_delta[t * KK + k] = (t < 24) ? 0.5f * acc : acc;   // pre-halve r/z gates
    }
    __syncthreads();

    if (t < 144) {
        int d = t / 12, o = t % 12;
        const float* w1 = W1 + (size_t)k * 12 * DHID + d * DHID;
        float acc = 0.f;
        #pragma unroll 8
        for (int h = 0; h < DHID; h++) acc = fmaf(w1[h], sW2[h * 12 + o], acc);
        g_Mc[k * 192 + o * 16 + d] = acc;         // stored [k][o][d] for lane-contiguous loads
    } else if (t < 156) {
        int o = t - 144;
        const float* bb = b1 + (size_t)k * DHID;
        float acc = b2[k * 12 + o];
        #pragma unroll 8
        for (int h = 0; h < DHID; h++) acc = fmaf(bb[h], sW2[h * 12 + o], acc);
        g_Mc[k * 192 + o * 16 + 12] = acc;
    }
}

// ============================================================================
// K1: encoder + input-gate precompute, TRANSPOSED output [b][j][k].
//   gi[j] = xs · Wih_row_j + bih[j] (+ bhh[j] for j<24); rows j<24 pre-halved
//   so the scan can do sigma(x) = 0.5*tanh(halved_sum)+0.5 with no extra muls.
// Block = one b, thread = k -> all loads and stores coalesced in k.
// ============================================================================
__global__ void enc_gi(const float* __restrict__ x, const float* __restrict__ Wih,
                       const float* __restrict__ bih, const float* __restrict__ bhh) {
    __shared__ float sW[NG * 12];
    __shared__ float sB[NG];
    int k = threadIdx.x;                          // 0..159
    int b = blockIdx.x;
    for (int i = k; i < NG * 12; i += 160) {
        float w = Wih[i];
        sW[i] = (i < 24 * 12) ? 0.5f * w : w;
    }
    if (k < NG) sB[k] = (k < 24) ? 0.5f * (bih[k] + bhh[k]) : bih[k];
    __syncthreads();

    const float4* xv = reinterpret_cast<const float4*>(x) + (size_t)b * 480 + k * 3;
    float4 v0 = xv[0], v1 = xv[1], v2 = xv[2];
    float xm[12] = {v0.x, v0.y, v0.z, v0.w, v1.x, v1.y, v1.z, v1.w,
                    v2.x, v2.y, v2.z, v2.w};
    float xs[12];
    #pragma unroll
    for (int o = 0; o < 12; o++) {
        float acc = g_bt[o * KK + k];
        #pragma unroll
        for (int i = 0; i < 12; i++)
            acc = fmaf(xm[i], g_Wt[(i * 12 + o) * KK + k], acc);
        xs[o] = fmaxf(acc, 0.f);
    }
    float* out = g_gi + (size_t)b * (NG * KK) + k;
    #pragma unroll
    for (int j = 0; j < NG; j++) {
        float acc = sB[j];
        #pragma unroll
        for (int i = 0; i < 12; i++)
            acc = fmaf(xs[i], sW[j * 12 + i], acc);
        out[j * KK] = acc;                        // coalesced across k
    }
}

// ============================================================================
// K2: sequential GRU scan + fused decoder. 12 lanes/chain, 2 chains/warp.
// gi streams are contiguous in k per lane -> float4 loads, 8-step prefetch.
// During step k's h-broadcast (h_{k-1}), the decode of output k-1 piggybacks
// on the same shuffled values (off critical path).
// ============================================================================
template<bool DEC>
__device__ __forceinline__ float gru_step(float h, float grh, float gzh, float gn,
                                          const float* __restrict__ wr,
                                          const float* __restrict__ wz,
                                          const float* __restrict__ wn,
                                          float bnh, int gbase,
                                          const float* mv, float* dec) {
    float ar0 = grh, az0 = gzh, an0 = bnh;       // grh/gzh pre-halved, bnh = 0.5*bhh_n
    float ar1 = 0.f, az1 = 0.f, an1 = 0.f;
    float d0 = 0.f, d1 = 0.f;
    if (DEC) d0 = mv[12];                        // decoder bias
    #pragma unroll
    for (int i = 0; i < 6; i++) {
        float hv = __shfl_sync(0xffffffffu, h, gbase + i);
        ar0 = fmaf(wr[i], hv, ar0); az0 = fmaf(wz[i], hv, az0); an0 = fmaf(wn[i], hv, an0);
        if (DEC) d0 = fmaf(mv[i], hv, d0);
    }
    #pragma unroll
    for (int i = 6; i < 12; i++) {
        float hv = __shfl_sync(0xffffffffu, h, gbase + i);
        ar1 = fmaf(wr[i], hv, ar1); az1 = fmaf(wz[i], hv, az1); an1 = fmaf(wn[i], hv, an1);
        if (DEC) d1 = fmaf(mv[i], hv, d1);
    }
    if (DEC) *dec = d0 + d1;
    float tr  = tanh_ap(ar0 + ar1);              // r = 0.5*tr + 0.5 (implicit)
    float tz  = tanh_ap(az0 + az1);
    float hnh = an0 + an1;                       // = 0.5*(h.Whh_n + bhh_n)
    float n   = tanh_acc(fmaf(tr, hnh, gn + hnh));
    float z   = fmaf(0.5f, tz, 0.5f);
    return fmaf(z, h - n, n);                    // (1-z)*n + z*h
}

__global__ void __launch_bounds__(64, 1) scan_gru(const float* __restrict__ Whh,
                                                  const float* __restrict__ bhh,
                                                  float* __restrict__ out) {
    const int lane  = threadIdx.x & 31;
    const int sub   = threadIdx.x & 15;
    const int s     = sub < 12 ? sub : 11;       // lanes 12-15 duplicate lane 11
    const int gbase = lane & 16;
    const int chain = blockIdx.x * 4 + (threadIdx.x >> 4);

    float wr[12], wz[12], wn[12];
    #pragma unroll
    for (int i = 0; i < 12; i++) {
        wr[i] = 0.5f * Whh[s * 12 + i];
        wz[i] = 0.5f * Whh[(s + 12) * 12 + i];
        wn[i] = 0.5f * Whh[(s + 24) * 12 + i];
    }
    float bnh = 0.5f * bhh[24 + s];

    const float* gp = g_gi + (size_t)chain * (NG * KK);
    const float* pr = gp + s * KK;
    const float* pz = gp + (12 + s) * KK;
    const float* pn = gp + (24 + s) * KK;
    float h = 0.f;

    // -------- pass 1 (h0 = 0) --------
    {
        float4 r0 = *(const float4*)pr,       z0 = *(const float4*)pz,       n0 = *(const float4*)pn;
        float4 r1 = *(const float4*)(pr + 4), z1 = *(const float4*)(pz + 4), n1 = *(const float4*)(pn + 4);
        #pragma unroll 1
        for (int c = 0; c < 40; c++) {
            float4 R = r0, Z = z0, N = n0;
            r0 = r1; z0 = z1; n0 = n1;
            if (c + 2 < 40) {
                int kp = (c + 2) * 4;
                r1 = *(const float4*)(pr + kp); z1 = *(const float4*)(pz + kp); n1 = *(const float4*)(pn + kp);
            }
            h = gru_step<false>(h, R.x, Z.x, N.x, wr, wz, wn, bnh, gbase, 0, 0);
            h = gru_step<false>(h, R.y, Z.y, N.y, wr, wz, wn, bnh, gbase, 0, 0);
            h = gru_step<false>(h, R.z, Z.z, N.z, wr, wz, wn, bnh, gbase, 0, 0);
            h = gru_step<false>(h, R.w, Z.w, N.w, wr, wz, wn, bnh, gbase, 0, 0);
        }
    }

    // -------- pass 2 (gi + positional delta), decoder fused --------
    const float* qr = g_delta + s * KK;
    const float* qz = g_delta + (12 + s) * KK;
    const float* qn = g_delta + (24 + s) * KK;
    float* op = out + (size_t)chain * 1920;

    // decoder M/c double buffer: even steps use A, odd use B; 2-step lead
    float mvA[16], mvB[16];
    #pragma unroll
    for (int q = 0; q < 4; q++)
        *(float4*)(mvB + q * 4) = *(const float4*)(g_Mc + s * 16 + q * 4);   // M[0] -> iter 1
    #pragma unroll
    for (int q = 0; q < 4; q++)
        *(float4*)(mvA + q * 4) = *(const float4*)(g_Mc + s * 16 + q * 4);   // init (iter-0 value unused)

    float4 r0  = *(const float4*)pr,       z0  = *(const float4*)pz,       n0  = *(const float4*)pn;
    float4 dr0 = *(const float4*)qr,       dz0 = *(const float4*)qz,       dn0 = *(const float4*)qn;
    float4 r1  = *(const float4*)(pr + 4), z1  = *(const float4*)(pz + 4), n1  = *(const float4*)(pn + 4);
    float4 dr1 = *(const float4*)(qr + 4), dz1 = *(const float4*)(qz + 4), dn1 = *(const float4*)(qn + 4);

    #pragma unroll 1
    for (int c = 0; c < 40; c++) {
        float4 R = r0, Z = z0, N = n0, DR = dr0, DZ = dz0, DN = dn0;
        r0 = r1; z0 = z1; n0 = n1; dr0 = dr1; dz0 = dz1; dn0 = dn1;
        if (c + 2 < 40) {
            int kp = (c + 2) * 4;
            r1  = *(const float4*)(pr + kp); z1  = *(const float4*)(pz + kp); n1  = *(const float4*)(pn + kp);
            dr1 = *(const float4*)(qr + kp); dz1 = *(const float4*)(qz + kp); dn1 = *(const float4*)(qn + kp);
        }
        int kb = c * 4;
        float dec;
        // u = 0 (even -> mvA)
        h = gru_step<true>(h, R.x + DR.x, Z.x + DZ.x, N.x + DN.x, wr, wz, wn, bnh, gbase, mvA, &dec);
        if (sub < 12 && kb > 0) op[(kb - 1) * 12 + sub] = dec;
        #pragma unroll
        for (int q = 0; q < 4; q++)
            *(float4*)(mvA + q * 4) = *(const float4*)(g_Mc + (kb + 1) * 192 + s * 16 + q * 4);
        // u = 1 (odd -> mvB)
        h = gru_step<true>(h, R.y + DR.y, Z.y + DZ.y, N.y + DN.y, wr, wz, wn, bnh, gbase, mvB, &dec);
        if (sub < 12) op[kb * 12 + sub] = dec;
        #pragma unroll
        for (int q = 0; q < 4; q++)
            *(float4*)(mvB + q * 4) = *(const float4*)(g_Mc + (kb + 2) * 192 + s * 16 + q * 4);
        // u = 2 (even -> mvA)
        h = gru_step<true>(h, R.z + DR.z, Z.z + DZ.z, N.z + DN.z, wr, wz, wn, bnh, gbase, mvA, &dec);
        if (sub < 12) op[(kb + 1) * 12 + sub] = dec;
        #pragma unroll
        for (int q = 0; q < 4; q++)
            *(float4*)(mvA + q * 4) = *(const float4*)(g_Mc + (kb + 3) * 192 + s * 16 + q * 4);
        // u = 3 (odd -> mvB)
        h = gru_step<true>(h, R.w + DR.w, Z.w + DZ.w, N.w + DN.w, wr, wz, wn, bnh, gbase, mvB, &dec);
        if (sub < 12) op[(kb + 2) * 12 + sub] = dec;
        if (kb + 4 < KK) {
            #pragma unroll
            for (int q = 0; q < 4; q++)
                *(float4*)(mvB + q * 4) = *(const float4*)(g_Mc + (kb + 4) * 192 + s * 16 + q * 4);
        }
    }
    // final decode for step 159 (mvA holds M[159]: loaded at iter 158)
    {
        float d0 = mvA[12], d1 = 0.f;
        #pragma unroll
        for (int i = 0; i < 6; i++) {
            float hv = __shfl_sync(0xffffffffu, h, gbase + i);
            d0 = fmaf(mvA[i], hv, d0);
        }
        #pragma unroll
        for (int i = 6; i < 12; i++) {
            float hv = __shfl_sync(0xffffffffu, h, gbase + i);
            d1 = fmaf(mvA[i], hv, d1);
        }
        if (sub < 12) op[159 * 12 + sub] = d0 + d1;
    }
}

// ============================================================================
extern "C" void kernel_launch(void* const* d_in, const int* in_sizes, int n_in,
                              void* d_out, int out_size) {
    const float* x    = (const float*)d_in[0];
    const float* encW = (const float*)d_in[1];
    const float* encb = (const float*)d_in[2];
    const float* Wih  = (const float*)d_in[3];
    const float* Whh  = (const float*)d_in[4];
    const float* bih  = (const float*)d_in[5];
    const float* bhh  = (const float*)d_in[6];
    const float* W1   = (const float*)d_in[7];
    const float* b1   = (const float*)d_in[8];
    const float* W2   = (const float*)d_in[9];
    const float* b2   = (const float*)d_in[10];
    float* out = (float*)d_out;

    prep_all<<<KK, 256>>>(encW, encb, Wih, W1, b1, W2, b2);
    enc_gi<<<BB, 160>>>(x, Wih, bih, bhh);
    scan_gru<<<BB / 4, 64>>>(Whh, bhh, out);
}